// round 11
// baseline (speedup 1.0000x reference)
#include <cuda_runtime.h>
#include <cstddef>

namespace {
constexpr int Bsz = 512, Tsz = 1024, Hs = 64, R = 4;
constexpr int QS = 36;   // quarter stride (floats) -> bank groups {0,4,8,12}
constexpr int RS = 4 * QS;
}

using ull = unsigned long long;

__device__ __forceinline__ void unpack2(ull v, float& lo, float& hi) {
    asm("mov.b64 {%0,%1},%2;" : "=f"(lo), "=f"(hi) : "l"(v));
}
__device__ __forceinline__ ull ffma2(ull a, ull b, ull c) {
    ull d;
    asm("fma.rn.f32x2 %0,%1,%2,%3;" : "=l"(d) : "l"(a), "l"(b), "l"(c));
    return d;
}
__device__ __forceinline__ float fast_ex2(float x) {
    float r; asm("ex2.approx.f32 %0,%1;" : "=f"(r) : "f"(x)); return r;
}
__device__ __forceinline__ float fast_rcp(float x) {
    float r; asm("rcp.approx.f32 %0,%1;" : "=f"(r) : "f"(x)); return r;
}
__device__ __forceinline__ float fsigmoid(float x) {
    return fast_rcp(1.0f + fast_ex2(-1.44269504f * x));
}
__device__ __forceinline__ float ftanh(float x) {
    float ax = fabsf(x);
    float t  = fast_ex2(-2.88539008f * ax);          // exp(-2|x|)
    float y  = (1.0f - t) * fast_rcp(1.0f + t);
    return copysignf(y, x);
}
__device__ __forceinline__ int hidx(int k) {         // k index -> padded offset
    return (k >> 4) * QS + (k & 15);
}
__device__ __forceinline__ float sum2(const float2& v) { return v.x + v.y; }

// ---------------------------------------------------------------------------
// Fused 2-layer GRU. Grid 128 x 768; CTA owns 4 batch rows.
// PHASE A: thread = (m = tx>>8, j = (tx&255)>>2, q = tx&3). Each thread dots
//   3 gate-rows (j, j+64, j+128) of matrix m over its 16-k quarter against 4
//   rows (m=0: Whh0.h1[s-1], m=1: Wih1.h1[s-1], m=2: Whh1.h2[s-2]).
//   One shfl_xor(1) folds quarter pairs -> TWO partials per gate; even-q
//   lanes store them (predicated 16-lane STS = 1 wavefront). This halves the
//   partial-exchange smem traffic vs the 4-partial variant (round 8's L1=68%
//   top pipe: phase-B 512B contiguous loads were 4 wavefronts each).
// PHASE B: 512 combine tasks 1:1 on threads 0..511; each gate read is ONE
//   LDS.64 (2 wavefronts/warp) + add. L0 tasks apply the x-projection
//   (weights from smem). m=2 threads stage x[s+1]. Two barriers/step.
// ---------------------------------------------------------------------------
__global__ void __launch_bounds__(768, 1) gru_fused(
    const float* __restrict__ x,
    const float* __restrict__ W_ih0, const float* __restrict__ W_hh0,
    const float* __restrict__ b_ih0, const float* __restrict__ b_hh0,
    const float* __restrict__ W_ih1, const float* __restrict__ W_hh1,
    const float* __restrict__ b_ih1, const float* __restrict__ b_hh1,
    float* __restrict__ outp,        // (B,T,64)
    float* __restrict__ finalp)      // (B,64)
{
    __shared__ float sh_h1[2][R * RS];        // [parity][row*RS + hidx(k)]
    __shared__ float sh_h2[2][R * RS];
    __shared__ float sh_p [3][3][R][64][2];   // [matrix][gate][row][j][pairhalf]
    __shared__ float sh_wx[10][64];           // W_ih0 rows (9) + b_ih0 n (1)
    __shared__ float sh_x [2][R][3];          // staged x[t]

    const int tx = threadIdx.x;
    const int m  = tx >> 8;               // 0: Whh0, 1: Wih1, 2: Whh1
    const int l8 = tx & 255;
    const int j  = l8 >> 2;               // 0..63
    const int q  = l8 & 3;                // k-quarter
    const int kb = q * 16;

    // ---- phase-A weights: 3 gate-rows x 16-k quarter, packed f32x2 ----
    const float* __restrict__ Wm = (m == 0) ? W_hh0 : (m == 1) ? W_ih1 : W_hh1;
    ull w2[24];
    const ull* __restrict__ Wll = reinterpret_cast<const ull*>(Wm);
#pragma unroll
    for (int g3 = 0; g3 < 3; g3++) {
        const int g = j + g3 * 64;
#pragma unroll
        for (int kk = 0; kk < 8; kk++)
            w2[g3 * 8 + kk] = Wll[(g * 64 + kb) / 2 + kk];
    }

    // biases folded by the q==0 lane only (pair-sum q0+q1 then carries them)
    float b0q = 0.f, b1q = 0.f, b2q = 0.f;
    if (q == 0) {
        if (m == 0) {
            b0q = b_ih0[j]       + b_hh0[j];
            b1q = b_ih0[j + 64]  + b_hh0[j + 64];
            b2q = b_hh0[j + 128];                // recurrent n (inside r*)
        } else if (m == 1) {
            b0q = b_ih1[j]       + b_hh1[j];
            b1q = b_ih1[j + 64]  + b_hh1[j + 64];
            b2q = b_ih1[j + 128];                // input n
        } else {
            b2q = b_hh1[j + 128];                // recurrent n
        }
    }
    const bool qeven = ((q & 1) == 0);
    const int  qh    = q >> 1;

    // ---- phase-B task (threads 0..511): (L = tx>>8, rB, jB) ----
    const int L  = tx >> 8;
    const int rB = (tx >> 6) & 3;
    const int jB = tx & 63;

    // x staging: m==2 threads 0..11
    const int  sx  = tx - 512;
    const bool xst = (m == 2) && (sx < 12);
    const int  xr  = xst ? sx / 3 : 0, xc = xst ? sx % 3 : 0;
    const int row4 = blockIdx.x * 4;

    // ---- init ----
    for (int i = tx; i < 2 * R * RS; i += 768) {
        reinterpret_cast<float*>(sh_h1)[i] = 0.f;
        reinterpret_cast<float*>(sh_h2)[i] = 0.f;
    }
    for (int i = tx; i < 640; i += 768) {
        const int rw = i >> 6, cl = i & 63;
        sh_wx[rw][cl] = (rw < 9)
            ? W_ih0[((rw / 3) * 64 + cl) * 3 + (rw % 3)]
            : b_ih0[cl + 128];
    }
    if (xst)
        sh_x[0][xr][xc] = __ldg(&x[((size_t)(row4 + xr) * Tsz) * 3 + xc]);
    __syncthreads();

    for (int s = 0; s <= Tsz; s++) {
        const int par = s & 1;

        // ===================== PHASE A: dots =============================
        const float* __restrict__ hsrc =
            (m == 2) ? &sh_h2[par][0] : &sh_h1[par][0];
#pragma unroll
        for (int r = 0; r < R; r++) {
            const ulonglong2* __restrict__ hb =
                reinterpret_cast<const ulonglong2*>(hsrc + r * RS + q * QS);
            ull a0 = 0ull, a1 = 0ull, a2 = 0ull;
#pragma unroll
            for (int i = 0; i < 4; i++) {
                const ulonglong2 h4 = hb[i];               // LDS.128, broadcast
                a0 = ffma2(h4.x, w2[2 * i],          a0);
                a0 = ffma2(h4.y, w2[2 * i + 1],      a0);
                a1 = ffma2(h4.x, w2[8 + 2 * i],      a1);
                a1 = ffma2(h4.y, w2[8 + 2 * i + 1],  a1);
                a2 = ffma2(h4.x, w2[16 + 2 * i],     a2);
                a2 = ffma2(h4.y, w2[16 + 2 * i + 1], a2);
            }
            float l, h;
            unpack2(a0, l, h); float p0 = (l + h) + b0q;
            unpack2(a1, l, h); float p1 = (l + h) + b1q;
            unpack2(a2, l, h); float p2 = (l + h) + b2q;
            // fold quarter pairs: lanes (q, q^1) both get the pair sum
            p0 += __shfl_xor_sync(0xffffffffu, p0, 1);
            p1 += __shfl_xor_sync(0xffffffffu, p1, 1);
            p2 += __shfl_xor_sync(0xffffffffu, p2, 1);
            if (qeven) {
                sh_p[m][0][r][j][qh] = p0;
                sh_p[m][1][r][j][qh] = p1;
                sh_p[m][2][r][j][qh] = p2;
            }
        }
        __syncthreads();                     // drains the STS above

        // ===================== PHASE B: combines ==========================
        if (m < 2) {                          // 512 tasks, 1:1
            if (L == 0) {
                if (s < Tsz) {                // h1[s]
                    const float pr = sum2(*reinterpret_cast<const float2*>(
                        &sh_p[0][0][rB][jB][0]));
                    const float pz = sum2(*reinterpret_cast<const float2*>(
                        &sh_p[0][1][rB][jB][0]));
                    const float pn = sum2(*reinterpret_cast<const float2*>(
                        &sh_p[0][2][rB][jB][0]));
                    const float x0 = sh_x[par][rB][0];
                    const float x1 = sh_x[par][rB][1];
                    const float x2 = sh_x[par][rB][2];
                    const float ar = pr
                        + fmaf(x2, sh_wx[2][jB],
                          fmaf(x1, sh_wx[1][jB], x0 * sh_wx[0][jB]));
                    const float az = pz
                        + fmaf(x2, sh_wx[5][jB],
                          fmaf(x1, sh_wx[4][jB], x0 * sh_wx[3][jB]));
                    const float xan = sh_wx[9][jB]
                        + fmaf(x2, sh_wx[8][jB],
                          fmaf(x1, sh_wx[7][jB], x0 * sh_wx[6][jB]));
                    const float rr = fsigmoid(ar);
                    const float zz = fsigmoid(az);
                    const float nn = ftanh(fmaf(rr, pn, xan));
                    const float hp = sh_h1[par][rB * RS + hidx(jB)];
                    sh_h1[par ^ 1][rB * RS + hidx(jB)] = fmaf(zz, hp - nn, nn);
                }
            } else {
                if (s >= 1) {                 // h2[s-1] -> output
                    const int tau = s - 1;
                    const float ar = sum2(*reinterpret_cast<const float2*>(
                                        &sh_p[1][0][rB][jB][0]))
                                   + sum2(*reinterpret_cast<const float2*>(
                                        &sh_p[2][0][rB][jB][0]));
                    const float az = sum2(*reinterpret_cast<const float2*>(
                                        &sh_p[1][1][rB][jB][0]))
                                   + sum2(*reinterpret_cast<const float2*>(
                                        &sh_p[2][1][rB][jB][0]));
                    const float xn = sum2(*reinterpret_cast<const float2*>(
                                        &sh_p[1][2][rB][jB][0]));
                    const float hn_ = sum2(*reinterpret_cast<const float2*>(
                                        &sh_p[2][2][rB][jB][0]));
                    const float rr = fsigmoid(ar);
                    const float zz = fsigmoid(az);
                    const float nn = ftanh(fmaf(rr, hn_, xn));
                    const float hp = sh_h2[par][rB * RS + hidx(jB)];
                    const float hv = fmaf(zz, hp - nn, nn);
                    sh_h2[par ^ 1][rB * RS + hidx(jB)] = hv;
                    outp[((size_t)(row4 + rB) * Tsz + tau) * Hs + jB] = hv;
                    if (tau == Tsz - 1)
                        finalp[(row4 + rB) * Hs + jB] = hv;
                }
            }
        } else if (xst && s + 1 < Tsz) {
            // stage x[s+1] into parity (s+1)&1
            sh_x[par ^ 1][xr][xc] =
                __ldg(&x[((size_t)(row4 + xr) * Tsz + (s + 1)) * 3 + xc]);
        }
        __syncthreads();
    }
}

// ---------------------------------------------------------------------------
extern "C" void kernel_launch(void* const* d_in, const int* in_sizes, int n_in,
                              void* d_out, int out_size)
{
    (void)in_sizes; (void)n_in; (void)out_size;
    const float* x     = (const float*)d_in[0];
    const float* W_ih0 = (const float*)d_in[1];
    const float* W_hh0 = (const float*)d_in[2];
    const float* b_ih0 = (const float*)d_in[3];
    const float* b_hh0 = (const float*)d_in[4];
    const float* W_ih1 = (const float*)d_in[5];
    const float* W_hh1 = (const float*)d_in[6];
    const float* b_ih1 = (const float*)d_in[7];
    const float* b_hh1 = (const float*)d_in[8];

    float* out    = (float*)d_out;
    float* finalh = out + (size_t)Bsz * Tsz * Hs;

    gru_fused<<<128, 768>>>(x, W_ih0, W_hh0, b_ih0, b_hh0,
                            W_ih1, W_hh1, b_ih1, b_hh1, out, finalh);
}

// round 12
// speedup vs baseline: 1.3532x; 1.3532x over previous
#include <cuda_runtime.h>
#include <cstddef>

namespace {
constexpr int Bsz = 512, Tsz = 1024, Hs = 64;
}

using ull = unsigned long long;

__device__ __forceinline__ void unpack2(ull v, float& lo, float& hi) {
    asm("mov.b64 {%0,%1},%2;" : "=f"(lo), "=f"(hi) : "l"(v));
}
__device__ __forceinline__ ull ffma2(ull a, ull b, ull c) {
    ull d;
    asm("fma.rn.f32x2 %0,%1,%2,%3;" : "=l"(d) : "l"(a), "l"(b), "l"(c));
    return d;
}
__device__ __forceinline__ float fast_ex2(float x) {
    float r; asm("ex2.approx.f32 %0,%1;" : "=f"(r) : "f"(x)); return r;
}
__device__ __forceinline__ float fast_rcp(float x) {
    float r; asm("rcp.approx.f32 %0,%1;" : "=f"(r) : "f"(x)); return r;
}
__device__ __forceinline__ float fsigmoid(float x) {
    return fast_rcp(1.0f + fast_ex2(-1.44269504f * x));
}
__device__ __forceinline__ float ftanh(float x) {
    float ax = fabsf(x);
    float t  = fast_ex2(-2.88539008f * ax);          // exp(-2|x|)
    float y  = (1.0f - t) * fast_rcp(1.0f + t);
    return copysignf(y, x);
}

#define BAR_SYNC(id, cnt)   asm volatile("bar.sync %0, %1;"   :: "r"(id), "r"(cnt) : "memory")
#define BAR_ARRIVE(id, cnt) asm volatile("bar.arrive %0, %1;" :: "r"(id), "r"(cnt) : "memory")

// Barrier ids (15 available):
//   1: G0 internal (128)   2: G1 internal (128)   3: G2 internal (128)
//   4+par : h1 ring slot READY  (G0 arrive, G1 sync; 256)
//   6+par : h1 ring slot FREE   (G1 arrive, G0 sync; 256)
//   8+par : gx ring slot READY  (G1 arrive, G2 sync; 256)
//  10+par : gx ring slot FREE   (G2 arrive, G1 sync; 256)

// ---------------------------------------------------------------------------
// Pipelined fused 2-layer GRU. Grid 128 x 384; CTA owns 4 batch rows.
// Three 4-warp groups (warp w -> SMSP w%4, so each SMSP hosts one warp of
// each group), coupled only through depth-2 smem rings + named barriers:
//   G0 (warps 0-3):  h1[s] = GRU0(h1[s-1], x[s])     -> r_h1[s&1]
//   G1 (warps 4-7):  gx[s] = Wih1 . r_h1[s&1]        -> r_gx[s&1] (half-partials)
//   G2 (warps 8-11): h2[s] = GRU1(h2[s-1], gx[s])    -> global out
// No CTA-wide barrier in the loop: each group's stalls (MUFU chains, barrier
// waits) are hidden by the other groups' FFMA2 streams on the same SMSP.
// Thread within a group = (j = lt>>1, half = lt&1); 48 f32x2 weight regs;
// G0/G2 finish dots with one shfl_xor(1); G1 writes raw half-partials.
// ---------------------------------------------------------------------------
__global__ void __launch_bounds__(384, 1) gru_pipe(
    const float* __restrict__ x,
    const float* __restrict__ W_ih0, const float* __restrict__ W_hh0,
    const float* __restrict__ b_ih0, const float* __restrict__ b_hh0,
    const float* __restrict__ W_ih1, const float* __restrict__ W_hh1,
    const float* __restrict__ b_ih1, const float* __restrict__ b_hh1,
    float* __restrict__ outp,        // (B,T,64)
    float* __restrict__ finalp)      // (B,64)
{
    __shared__ float  p_h1[2][4][2][36];   // G0-private state [par][row][half][32+pad]
    __shared__ float  p_h2[2][4][2][36];   // G2-private state
    __shared__ float  r_h1[2][4][2][36];   // h1 ring (G0 -> G1), slot = s&1
    __shared__ float2 r_gx[2][4][3][66];   // gx ring (G1 -> G2): {half0,half1} partials
    __shared__ float  sh_x[2][4][3];       // staged x[t] (G0)

    const int tx   = threadIdx.x;
    const int grp  = tx >> 7;            // 0,1,2
    const int lt   = tx & 127;
    const int half = lt & 1;
    const int j    = lt >> 1;            // 0..63
    const int kb   = half * 32;
    const int row4 = blockIdx.x * 4;

    // ---- init: zero private states, stage x[0] ----
    for (int i = tx; i < 2 * 4 * 2 * 36; i += 384) {
        (&p_h1[0][0][0][0])[i] = 0.f;
        (&p_h2[0][0][0][0])[i] = 0.f;
    }
    if (tx < 12)
        sh_x[0][tx / 3][tx % 3] =
            __ldg(&x[((size_t)(row4 + tx / 3) * Tsz) * 3 + tx % 3]);
    __syncthreads();   // (barrier 0; not reused below)

    // helper lambda-ish macro for loading 3 gate-rows x 32-k half
#define LOAD_W(Wsrc)                                                         \
    {                                                                        \
        const ull* __restrict__ Wll = reinterpret_cast<const ull*>(Wsrc);    \
        _Pragma("unroll")                                                    \
        for (int g3 = 0; g3 < 3; g3++) {                                     \
            const int g = j + g3 * 64;                                       \
            _Pragma("unroll")                                                \
            for (int kk = 0; kk < 16; kk++)                                  \
                w2[g3 * 16 + kk] = Wll[(g * 64 + kb) / 2 + kk];              \
        }                                                                    \
    }

#define DOT_ROW(hbase, r, pr, pz, pn)                                        \
    {                                                                        \
        const ulonglong2* __restrict__ hb =                                  \
            reinterpret_cast<const ulonglong2*>((hbase) + (r) * 72 + half * 36); \
        ull a0 = 0ull, a1 = 0ull, a2 = 0ull;                                 \
        _Pragma("unroll")                                                    \
        for (int i = 0; i < 8; i++) {                                        \
            const ulonglong2 h4 = hb[i];                                     \
            a0 = ffma2(h4.x, w2[2 * i],          a0);                        \
            a0 = ffma2(h4.y, w2[2 * i + 1],      a0);                        \
            a1 = ffma2(h4.x, w2[16 + 2 * i],     a1);                        \
            a1 = ffma2(h4.y, w2[16 + 2 * i + 1], a1);                        \
            a2 = ffma2(h4.x, w2[32 + 2 * i],     a2);                        \
            a2 = ffma2(h4.y, w2[32 + 2 * i + 1], a2);                        \
        }                                                                    \
        float l_, h_;                                                        \
        unpack2(a0, l_, h_); pr = l_ + h_;                                   \
        unpack2(a1, l_, h_); pz = l_ + h_;                                   \
        unpack2(a2, l_, h_); pn = l_ + h_;                                   \
    }

    if (grp == 0) {
        // ================= G0: layer-0 engine =================
        ull w2[48];
        LOAD_W(W_hh0);
        float wi0[9];
#pragma unroll
        for (int g3 = 0; g3 < 3; g3++)
#pragma unroll
            for (int c = 0; c < 3; c++)
                wi0[g3 * 3 + c] = W_ih0[(j + g3 * 64) * 3 + c];
        const float bR  = b_ih0[j]       + b_hh0[j];
        const float bZ  = b_ih0[j + 64]  + b_hh0[j + 64];
        const float bXN = b_ih0[j + 128];
        const float bHN = b_hh0[j + 128];

        float hp[2] = {0.f, 0.f};            // rows 2*half, 2*half+1
        const int rA = 2 * half, rBr = rA + 1;

        for (int s = 0; s < Tsz; s++) {
            const int par = s & 1;
            if (s >= 2) BAR_SYNC(6 + par, 256);       // ring slot free

            float s0r, s0z, s0n, s1r, s1z, s1n, s2r, s2z, s2n, s3r, s3z, s3n;
            const float* hb0 = &p_h1[par][0][0][0];
            DOT_ROW(hb0, 0, s0r, s0z, s0n);
            DOT_ROW(hb0, 1, s1r, s1z, s1n);
            DOT_ROW(hb0, 2, s2r, s2z, s2n);
            DOT_ROW(hb0, 3, s3r, s3z, s3n);
            s0r += __shfl_xor_sync(~0u, s0r, 1); s0z += __shfl_xor_sync(~0u, s0z, 1); s0n += __shfl_xor_sync(~0u, s0n, 1);
            s1r += __shfl_xor_sync(~0u, s1r, 1); s1z += __shfl_xor_sync(~0u, s1z, 1); s1n += __shfl_xor_sync(~0u, s1n, 1);
            s2r += __shfl_xor_sync(~0u, s2r, 1); s2z += __shfl_xor_sync(~0u, s2z, 1); s2n += __shfl_xor_sync(~0u, s2n, 1);
            s3r += __shfl_xor_sync(~0u, s3r, 1); s3z += __shfl_xor_sync(~0u, s3z, 1); s3n += __shfl_xor_sync(~0u, s3n, 1);

            // my two rows' sums
            const float pra = half ? s2r : s0r, pza = half ? s2z : s0z, pna = half ? s2n : s0n;
            const float prb = half ? s3r : s1r, pzb = half ? s3z : s1z, pnb = half ? s3n : s1n;

#pragma unroll
            for (int k = 0; k < 2; k++) {
                const int  rr = k ? rBr : rA;
                const float pr = k ? prb : pra;
                const float pz = k ? pzb : pza;
                const float pn = k ? pnb : pna;
                const float x0 = sh_x[par][rr][0];
                const float x1 = sh_x[par][rr][1];
                const float x2 = sh_x[par][rr][2];
                const float ar  = pr + fmaf(x2, wi0[2], fmaf(x1, wi0[1], fmaf(x0, wi0[0], bR)));
                const float az  = pz + fmaf(x2, wi0[5], fmaf(x1, wi0[4], fmaf(x0, wi0[3], bZ)));
                const float xan =      fmaf(x2, wi0[8], fmaf(x1, wi0[7], fmaf(x0, wi0[6], bXN)));
                const float rg = fsigmoid(ar);
                const float zg = fsigmoid(az);
                const float nn = ftanh(fmaf(rg, pn + bHN, xan));
                const float hn = fmaf(zg, hp[k] - nn, nn);
                hp[k] = hn;
                p_h1[par ^ 1][rr][j >> 5][j & 31] = hn;
                r_h1[par][rr][j >> 5][j & 31]     = hn;
            }
            if (lt < 12 && s + 1 < Tsz)
                sh_x[par ^ 1][lt / 3][lt % 3] =
                    __ldg(&x[((size_t)(row4 + lt / 3) * Tsz + (s + 1)) * 3 + lt % 3]);

            BAR_SYNC(1, 128);            // drain my STS (state + ring + x)
            BAR_ARRIVE(4 + par, 256);    // h1[s] ready for G1
        }
    } else if (grp == 1) {
        // ================= G1: gx engine =================
        ull w2[48];
        LOAD_W(W_ih1);
        float bR = 0.f, bZ = 0.f, bN = 0.f;
        if (half == 0) {                 // bias folded once (into half-0 partial)
            bR = b_ih1[j]       + b_hh1[j];
            bZ = b_ih1[j + 64]  + b_hh1[j + 64];
            bN = b_ih1[j + 128];
        }
        for (int s = 0; s < Tsz; s++) {
            const int par = s & 1;
            BAR_SYNC(4 + par, 256);      // h1[s] ready

            float pr[4], pz[4], pn[4];
            const float* hb0 = &r_h1[par][0][0][0];
#pragma unroll
            for (int r = 0; r < 4; r++)
                DOT_ROW(hb0, r, pr[r], pz[r], pn[r]);

            BAR_ARRIVE(6 + par, 256);            // done reading h1 ring
            if (s >= 2) BAR_SYNC(10 + par, 256); // gx slot free

#pragma unroll
            for (int r = 0; r < 4; r++) {
                reinterpret_cast<float*>(&r_gx[par][r][0][j])[half] = pr[r] + bR;
                reinterpret_cast<float*>(&r_gx[par][r][1][j])[half] = pz[r] + bZ;
                reinterpret_cast<float*>(&r_gx[par][r][2][j])[half] = pn[r] + bN;
            }
            BAR_SYNC(2, 128);            // drain gx STS
            BAR_ARRIVE(8 + par, 256);    // gx[s] ready for G2
        }
    } else {
        // ================= G2: layer-1 engine + output =================
        ull w2[48];
        LOAD_W(W_hh1);
        const float bHN = b_hh1[j + 128];
        float hp[2] = {0.f, 0.f};
        const int rA = 2 * half, rBr = rA + 1;

        for (int s = 0; s < Tsz; s++) {
            const int par = s & 1;
            BAR_SYNC(8 + par, 256);      // gx[s] ready

            float s0r, s0z, s0n, s1r, s1z, s1n, s2r, s2z, s2n, s3r, s3z, s3n;
            const float* hb0 = &p_h2[par][0][0][0];
            DOT_ROW(hb0, 0, s0r, s0z, s0n);
            DOT_ROW(hb0, 1, s1r, s1z, s1n);
            DOT_ROW(hb0, 2, s2r, s2z, s2n);
            DOT_ROW(hb0, 3, s3r, s3z, s3n);
            s0r += __shfl_xor_sync(~0u, s0r, 1); s0z += __shfl_xor_sync(~0u, s0z, 1); s0n += __shfl_xor_sync(~0u, s0n, 1);
            s1r += __shfl_xor_sync(~0u, s1r, 1); s1z += __shfl_xor_sync(~0u, s1z, 1); s1n += __shfl_xor_sync(~0u, s1n, 1);
            s2r += __shfl_xor_sync(~0u, s2r, 1); s2z += __shfl_xor_sync(~0u, s2z, 1); s2n += __shfl_xor_sync(~0u, s2n, 1);
            s3r += __shfl_xor_sync(~0u, s3r, 1); s3z += __shfl_xor_sync(~0u, s3z, 1); s3n += __shfl_xor_sync(~0u, s3n, 1);

            const float pra = half ? s2r : s0r, pza = half ? s2z : s0z, pna = half ? s2n : s0n;
            const float prb = half ? s3r : s1r, pzb = half ? s3z : s1z, pnb = half ? s3n : s1n;

#pragma unroll
            for (int k = 0; k < 2; k++) {
                const int  rr = k ? rBr : rA;
                const float pr = k ? prb : pra;
                const float pz = k ? pzb : pza;
                const float pn = k ? pnb : pna;
                const float2 gr = r_gx[par][rr][0][j];
                const float2 gz = r_gx[par][rr][1][j];
                const float2 gn = r_gx[par][rr][2][j];
                const float rg = fsigmoid((gr.x + gr.y) + pr);
                const float zg = fsigmoid((gz.x + gz.y) + pz);
                const float nn = ftanh(fmaf(rg, pn + bHN, gn.x + gn.y));
                const float hn = fmaf(zg, hp[k] - nn, nn);
                hp[k] = hn;
                p_h2[par ^ 1][rr][j >> 5][j & 31] = hn;
                outp[((size_t)(row4 + rr) * Tsz + s) * Hs + j] = hn;
                if (s == Tsz - 1)
                    finalp[(row4 + rr) * Hs + j] = hn;
            }
            BAR_ARRIVE(10 + par, 256);   // done reading gx ring
            BAR_SYNC(3, 128);            // drain p_h2 STS before next dot
        }
    }
#undef LOAD_W
#undef DOT_ROW
}

// ---------------------------------------------------------------------------
extern "C" void kernel_launch(void* const* d_in, const int* in_sizes, int n_in,
                              void* d_out, int out_size)
{
    (void)in_sizes; (void)n_in; (void)out_size;
    const float* x     = (const float*)d_in[0];
    const float* W_ih0 = (const float*)d_in[1];
    const float* W_hh0 = (const float*)d_in[2];
    const float* b_ih0 = (const float*)d_in[3];
    const float* b_hh0 = (const float*)d_in[4];
    const float* W_ih1 = (const float*)d_in[5];
    const float* W_hh1 = (const float*)d_in[6];
    const float* b_ih1 = (const float*)d_in[7];
    const float* b_hh1 = (const float*)d_in[8];

    float* out    = (float*)d_out;
    float* finalh = out + (size_t)Bsz * Tsz * Hs;

    gru_pipe<<<128, 384>>>(x, W_ih0, W_hh0, b_ih0, b_hh0,
                           W_ih1, W_hh1, b_ih1, b_hh1, out, finalh);
}

// round 13
// speedup vs baseline: 1.4678x; 1.0847x over previous
#include <cuda_runtime.h>
#include <cstddef>

namespace {
constexpr int Bsz = 512, Tsz = 1024, Hs = 64;
}

using ull = unsigned long long;

__device__ __forceinline__ void unpack2(ull v, float& lo, float& hi) {
    asm("mov.b64 {%0,%1},%2;" : "=f"(lo), "=f"(hi) : "l"(v));
}
__device__ __forceinline__ ull ffma2(ull a, ull b, ull c) {
    ull d;
    asm("fma.rn.f32x2 %0,%1,%2,%3;" : "=l"(d) : "l"(a), "l"(b), "l"(c));
    return d;
}
__device__ __forceinline__ float fast_ex2(float x) {
    float r; asm("ex2.approx.f32 %0,%1;" : "=f"(r) : "f"(x)); return r;
}
__device__ __forceinline__ float fast_rcp(float x) {
    float r; asm("rcp.approx.f32 %0,%1;" : "=f"(r) : "f"(x)); return r;
}
__device__ __forceinline__ float fsigmoid(float x) {
    return fast_rcp(1.0f + fast_ex2(-1.44269504f * x));
}
__device__ __forceinline__ float ftanh(float x) {
    float ax = fabsf(x);
    float t  = fast_ex2(-2.88539008f * ax);          // exp(-2|x|)
    float y  = (1.0f - t) * fast_rcp(1.0f + t);
    return copysignf(y, x);
}

#define BAR_SYNC(id, cnt)   asm volatile("bar.sync %0, %1;"   :: "r"(id), "r"(cnt) : "memory")
#define BAR_ARRIVE(id, cnt) asm volatile("bar.arrive %0, %1;" :: "r"(id), "r"(cnt) : "memory")

// Named-barrier map (ids 1..15; id 0 = the one __syncthreads before the loop):
//   1/2/3          : internal drains for G0/G1/G2 (128)
//   4+k  (k=0..2)  : h1 ring slot k READY  (G0 arrive, G1 sync; 256)
//   7+k            : h1 ring slot k FREE   (G1 arrive, G0 sync; 256)
//   10+k           : gx ring slot k READY  (G1 arrive, G2 sync; 256)
//   13+k           : gx ring slot k FREE   (G2 arrive, G1 sync; 256)

// ---------------------------------------------------------------------------
// Pipelined fused 2-layer GRU. Grid 128 x 384; CTA owns 4 batch rows.
// Three 4-warp groups (warp w -> SMSP w%4: one warp per group per SMSP),
// coupled only through DEPTH-3 smem rings + named barriers:
//   G0: h1[s] = GRU0(h1[s-1], x[s])  -> r_h1[s%3]   (ring IS G0's state)
//   G1: gx[s] = Wih1 . r_h1[s%3]     -> r_gx[s%3]   (half-partials)
//   G2: h2[s] = GRU1(h2[s-1], gx[s]) -> global out
// Critical-path discipline: G2 runs its recurrent dots BEFORE waiting on
// gx-ready; G0 waits on ring-free only right before its stores. Cross-lane
// reduce uses 6 shfl (exchange only the complementary rows' partials).
// ---------------------------------------------------------------------------
__global__ void __launch_bounds__(384, 1) gru_pipe(
    const float* __restrict__ x,
    const float* __restrict__ W_ih0, const float* __restrict__ W_hh0,
    const float* __restrict__ b_ih0, const float* __restrict__ b_hh0,
    const float* __restrict__ W_ih1, const float* __restrict__ W_hh1,
    const float* __restrict__ b_ih1, const float* __restrict__ b_hh1,
    float* __restrict__ outp,        // (B,T,64)
    float* __restrict__ finalp)      // (B,64)
{
    __shared__ float  r_h1[3][4][2][36];   // h1 ring  [slot][row][kgrp][32+pad]
    __shared__ float2 r_gx[3][4][3][64];   // gx ring  [slot][row][gate][j] {half0,half1}
    __shared__ float  p_h2[2][4][2][36];   // G2-private state (parity)
    __shared__ float  sh_x[2][4][3];       // staged x[t]

    const int tx   = threadIdx.x;
    const int grp  = tx >> 7;            // 0,1,2
    const int lt   = tx & 127;
    const int half = lt & 1;
    const int j    = lt >> 1;            // 0..63
    const int kb   = half * 32;
    const int row4 = blockIdx.x * 4;

    // ---- init ----
    for (int i = tx; i < 3 * 4 * 2 * 36; i += 384)
        (&r_h1[0][0][0][0])[i] = 0.f;
    for (int i = tx; i < 2 * 4 * 2 * 36; i += 384)
        (&p_h2[0][0][0][0])[i] = 0.f;
    if (tx < 12)
        sh_x[0][tx / 3][tx % 3] =
            __ldg(&x[((size_t)(row4 + tx / 3) * Tsz) * 3 + tx % 3]);
    __syncthreads();

#define LOAD_W(Wsrc)                                                         \
    {                                                                        \
        const ull* __restrict__ Wll = reinterpret_cast<const ull*>(Wsrc);    \
        _Pragma("unroll")                                                    \
        for (int g3 = 0; g3 < 3; g3++) {                                     \
            const int g = j + g3 * 64;                                       \
            _Pragma("unroll")                                                \
            for (int kk = 0; kk < 16; kk++)                                  \
                w2[g3 * 16 + kk] = Wll[(g * 64 + kb) / 2 + kk];              \
        }                                                                    \
    }

#define DOT_ROW(hbase, r, pr, pz, pn)                                        \
    {                                                                        \
        const ulonglong2* __restrict__ hb =                                  \
            reinterpret_cast<const ulonglong2*>((hbase) + (r) * 72 + half * 36); \
        ull a0 = 0ull, a1 = 0ull, a2 = 0ull;                                 \
        _Pragma("unroll")                                                    \
        for (int i = 0; i < 8; i++) {                                        \
            const ulonglong2 h4 = hb[i];                                     \
            a0 = ffma2(h4.x, w2[2 * i],          a0);                        \
            a0 = ffma2(h4.y, w2[2 * i + 1],      a0);                        \
            a1 = ffma2(h4.x, w2[16 + 2 * i],     a1);                        \
            a1 = ffma2(h4.y, w2[16 + 2 * i + 1], a1);                        \
            a2 = ffma2(h4.x, w2[32 + 2 * i],     a2);                        \
            a2 = ffma2(h4.y, w2[32 + 2 * i + 1], a2);                        \
        }                                                                    \
        float l_, h_;                                                        \
        unpack2(a0, l_, h_); pr = l_ + h_;                                   \
        unpack2(a1, l_, h_); pz = l_ + h_;                                   \
        unpack2(a2, l_, h_); pn = l_ + h_;                                   \
    }

    // 6-shfl exchange: full sums for MY two rows (myA = 2*half, myB = myA+1).
    // Send the partial of the NEIGHBOR's row; receive mine.
#define PAIR_REDUCE(s0, s1, s2, s3, fullA, fullB)                            \
    {                                                                        \
        const float sendA = half ? s0 : s2;                                  \
        const float sendB = half ? s1 : s3;                                  \
        const float mineA = half ? s2 : s0;                                  \
        const float mineB = half ? s3 : s1;                                  \
        fullA = mineA + __shfl_xor_sync(~0u, sendA, 1);                      \
        fullB = mineB + __shfl_xor_sync(~0u, sendB, 1);                      \
    }

    if (grp == 0) {
        // ================= G0: layer-0 engine =================
        ull w2[48];
        LOAD_W(W_hh0);
        float wi0[9];
#pragma unroll
        for (int g3 = 0; g3 < 3; g3++)
#pragma unroll
            for (int c = 0; c < 3; c++)
                wi0[g3 * 3 + c] = W_ih0[(j + g3 * 64) * 3 + c];
        const float bR  = b_ih0[j]       + b_hh0[j];
        const float bZ  = b_ih0[j + 64]  + b_hh0[j + 64];
        const float bXN = b_ih0[j + 128];
        const float bHN = b_hh0[j + 128];

        float hp[2] = {0.f, 0.f};            // rows 2*half, 2*half+1
        const int rA = 2 * half;

        int slot = 0, prev = 2;              // slot = s%3, prev = (s-1)%3
        for (int s = 0; s < Tsz; s++) {
            const int par = s & 1;
            // prefetch x[s+1] early (latency under the dots)
            float xpre = 0.f;
            if (lt < 12 && s + 1 < Tsz)
                xpre = __ldg(&x[((size_t)(row4 + lt / 3) * Tsz + (s + 1)) * 3 + lt % 3]);

            float s0r, s0z, s0n, s1r, s1z, s1n, s2r, s2z, s2n, s3r, s3z, s3n;
            const float* hb0 = &r_h1[prev][0][0][0];
            DOT_ROW(hb0, 0, s0r, s0z, s0n);
            DOT_ROW(hb0, 1, s1r, s1z, s1n);
            DOT_ROW(hb0, 2, s2r, s2z, s2n);
            DOT_ROW(hb0, 3, s3r, s3z, s3n);
            float prA, prB, pzA, pzB, pnA, pnB;
            PAIR_REDUCE(s0r, s1r, s2r, s3r, prA, prB);
            PAIR_REDUCE(s0z, s1z, s2z, s3z, pzA, pzB);
            PAIR_REDUCE(s0n, s1n, s2n, s3n, pnA, pnB);

            float hn2[2];
#pragma unroll
            for (int k = 0; k < 2; k++) {
                const int  rr = rA + k;
                const float pr = k ? prB : prA;
                const float pz = k ? pzB : pzA;
                const float pn = k ? pnB : pnA;
                const float x0 = sh_x[par][rr][0];
                const float x1 = sh_x[par][rr][1];
                const float x2 = sh_x[par][rr][2];
                const float ar  = pr + fmaf(x2, wi0[2], fmaf(x1, wi0[1], fmaf(x0, wi0[0], bR)));
                const float az  = pz + fmaf(x2, wi0[5], fmaf(x1, wi0[4], fmaf(x0, wi0[3], bZ)));
                const float xan =      fmaf(x2, wi0[8], fmaf(x1, wi0[7], fmaf(x0, wi0[6], bXN)));
                const float rg = fsigmoid(ar);
                const float zg = fsigmoid(az);
                const float nn = ftanh(fmaf(rg, pn + bHN, xan));
                hn2[k] = fmaf(zg, hp[k] - nn, nn);
                hp[k]  = hn2[k];
            }

            if (s >= 3) BAR_SYNC(7 + slot, 256);   // slot free (late wait)
            r_h1[slot][rA][j >> 5][j & 31]     = hn2[0];
            r_h1[slot][rA + 1][j >> 5][j & 31] = hn2[1];
            if (lt < 12 && s + 1 < Tsz)
                sh_x[par ^ 1][lt / 3][lt % 3] = xpre;

            BAR_SYNC(1, 128);             // drain STS
            BAR_ARRIVE(4 + slot, 256);    // h1[s] ready
            prev = slot; slot = (slot == 2) ? 0 : slot + 1;
        }
    } else if (grp == 1) {
        // ================= G1: gx engine =================
        ull w2[48];
        LOAD_W(W_ih1);
        float bR = 0.f, bZ = 0.f, bN = 0.f;
        if (half == 0) {                  // bias folded into half-0 partial
            bR = b_ih1[j]       + b_hh1[j];
            bZ = b_ih1[j + 64]  + b_hh1[j + 64];
            bN = b_ih1[j + 128];
        }
        int slot = 0;
        for (int s = 0; s < Tsz; s++) {
            BAR_SYNC(4 + slot, 256);      // h1[s] ready

            float pr[4], pz[4], pn[4];
            const float* hb0 = &r_h1[slot][0][0][0];
#pragma unroll
            for (int r = 0; r < 4; r++)
                DOT_ROW(hb0, r, pr[r], pz[r], pn[r]);

            BAR_ARRIVE(7 + slot, 256);            // done reading h1 ring
            if (s >= 3) BAR_SYNC(13 + slot, 256); // gx slot free

#pragma unroll
            for (int r = 0; r < 4; r++) {
                reinterpret_cast<float*>(&r_gx[slot][r][0][j])[half] = pr[r] + bR;
                reinterpret_cast<float*>(&r_gx[slot][r][1][j])[half] = pz[r] + bZ;
                reinterpret_cast<float*>(&r_gx[slot][r][2][j])[half] = pn[r] + bN;
            }
            BAR_SYNC(2, 128);             // drain gx STS
            BAR_ARRIVE(10 + slot, 256);   // gx[s] ready
            slot = (slot == 2) ? 0 : slot + 1;
        }
    } else {
        // ================= G2: layer-1 engine + output =================
        ull w2[48];
        LOAD_W(W_hh1);
        const float bHN = b_hh1[j + 128];
        float hp[2] = {0.f, 0.f};
        const int rA = 2 * half;

        int slot = 0;
        for (int s = 0; s < Tsz; s++) {
            const int par = s & 1;

            // recurrent dots FIRST (private state) — overlaps G1's gx write
            float s0r, s0z, s0n, s1r, s1z, s1n, s2r, s2z, s2n, s3r, s3z, s3n;
            const float* hb0 = &p_h2[par][0][0][0];
            DOT_ROW(hb0, 0, s0r, s0z, s0n);
            DOT_ROW(hb0, 1, s1r, s1z, s1n);
            DOT_ROW(hb0, 2, s2r, s2z, s2n);
            DOT_ROW(hb0, 3, s3r, s3z, s3n);
            float prA, prB, pzA, pzB, pnA, pnB;
            PAIR_REDUCE(s0r, s1r, s2r, s3r, prA, prB);
            PAIR_REDUCE(s0z, s1z, s2z, s3z, pzA, pzB);
            PAIR_REDUCE(s0n, s1n, s2n, s3n, pnA, pnB);

            BAR_SYNC(10 + slot, 256);     // gx[s] ready (late wait)

#pragma unroll
            for (int k = 0; k < 2; k++) {
                const int  rr = rA + k;
                const float pr = k ? prB : prA;
                const float pz = k ? pzB : pzA;
                const float pn = k ? pnB : pnA;
                const float2 gr = r_gx[slot][rr][0][j];
                const float2 gz = r_gx[slot][rr][1][j];
                const float2 gn = r_gx[slot][rr][2][j];
                const float rg = fsigmoid((gr.x + gr.y) + pr);
                const float zg = fsigmoid((gz.x + gz.y) + pz);
                const float nn = ftanh(fmaf(rg, pn + bHN, gn.x + gn.y));
                const float hn = fmaf(zg, hp[k] - nn, nn);
                hp[k] = hn;
                p_h2[par ^ 1][rr][j >> 5][j & 31] = hn;
                outp[((size_t)(row4 + rr) * Tsz + s) * Hs + j] = hn;
                if (s == Tsz - 1)
                    finalp[(row4 + rr) * Hs + j] = hn;
            }
            BAR_ARRIVE(13 + slot, 256);   // done reading gx ring
            BAR_SYNC(3, 128);             // order p_h2 writes before next dots
            slot = (slot == 2) ? 0 : slot + 1;
        }
    }
#undef LOAD_W
#undef DOT_ROW
#undef PAIR_REDUCE
}

// ---------------------------------------------------------------------------
extern "C" void kernel_launch(void* const* d_in, const int* in_sizes, int n_in,
                              void* d_out, int out_size)
{
    (void)in_sizes; (void)n_in; (void)out_size;
    const float* x     = (const float*)d_in[0];
    const float* W_ih0 = (const float*)d_in[1];
    const float* W_hh0 = (const float*)d_in[2];
    const float* b_ih0 = (const float*)d_in[3];
    const float* b_hh0 = (const float*)d_in[4];
    const float* W_ih1 = (const float*)d_in[5];
    const float* W_hh1 = (const float*)d_in[6];
    const float* b_ih1 = (const float*)d_in[7];
    const float* b_hh1 = (const float*)d_in[8];

    float* out    = (float*)d_out;
    float* finalh = out + (size_t)Bsz * Tsz * Hs;

    gru_pipe<<<128, 384>>>(x, W_ih0, W_hh0, b_ih0, b_hh0,
                           W_ih1, W_hh1, b_ih1, b_hh1, out, finalh);
}